// round 13
// baseline (speedup 1.0000x reference)
#include <cuda_runtime.h>
#include <cuda_fp16.h>
#include <cstdint>
#include <cstddef>

#define NB 4
#define HH 256
#define WW 256
#define CC 96
#define NF 4
#define CT 32                   // channels per CTA
#define NCB (CC / CT)           // 3 channel blocks
#define NJ 16                   // chunks per row/column
#define CL 16                   // chunk length
#define NTHR 512                // NJ * CT

// hscan input tile xs (floats): [j: JSX][i: ISX][c]
#define ISX 34
#define JSX 546                 // 16*34+2
// hscan ys staging (floats): [j: JSY][i: ISY][c]  (scalar access only)
#define ISY 33
#define JSY 530                 // 16*33+2

__constant__ float c_a[NF]   = {0.1f, 0.3f, 0.4f, 0.8f};
__constant__ float c_cf[NF]  = {0.81818181818f, 0.53846153846f, 0.42857142857f, 0.11111111111f}; // (1-a)/(1+a)
__constant__ float c_i1m[NF] = {1.11111111111f, 1.42857142857f, 1.66666666667f, 5.0f};           // 1/(1-a)

// PER-BATCH intermediate: [f][cblk][w][h][c32]  (50 MB, reused across batches
// -> stays L2-resident between the paired hscan_n / vscan_n launches)
#define COLSZ ((size_t)HH * CT)                 // 8192 halves per (w) column
__device__ __half g_mid[(size_t)NF * NCB * WW * COLSZ];
__device__ __forceinline__ size_t mid_base(int f, int cblk, int w) {
    return (((size_t)f * NCB + cblk) * WW + w) * COLSZ;
}

__device__ __forceinline__ unsigned h2_bits(__half2 h) {
    return *reinterpret_cast<unsigned*>(&h);
}

__device__ __forceinline__ float powi16(float A, int e) {
    float r = 1.0f, p = A;
    if (e & 1) r *= p;  p *= p;
    if (e & 2) r *= p;  p *= p;
    if (e & 4) r *= p;  p *= p;
    if (e & 8) r *= p;
    return r;
}

// ---------------------------------------------------------------------------
// Shfl-based bidirectional chunked scan (hscan; j in low lane bits):
// Yv[i] = F[i] + G[i] - x[i].  xv is NOT modified.
// ---------------------------------------------------------------------------
__device__ __forceinline__ void scan_core(
    const float* __restrict__ xv, float* __restrict__ Yv,
    int j, float a, float A16, float i1m)
{
    const unsigned FM = 0xffffffffu;

    float L = 0.0f, LB = 0.0f;
    #pragma unroll
    for (int i = 0; i < CL; ++i) {
        L  = fmaf(a, L,  xv[i]);
        LB = fmaf(a, LB, xv[CL - 1 - i]);
    }

    float s1 = L, s2 = LB, Ad = A16;
    #pragma unroll
    for (int d = 1; d < 16; d <<= 1) {
        float u1 = __shfl_up_sync(FM, s1, d, 16);
        float u2 = __shfl_down_sync(FM, s2, d, 16);
        if (j >= d)     s1 = fmaf(Ad, u1, s1);
        if (j + d < 16) s2 = fmaf(Ad, u2, s2);
        Ad *= Ad;
    }
    float P  = __shfl_up_sync(FM, s1, 1, 16);
    float Pb = __shfl_down_sync(FM, s2, 1, 16);
    if (j == 15) Pb = 0.0f;

    float x0 = __shfl_sync(FM, xv[0], 0, 16);
    float c0 = x0 * i1m;
    float cin = (j == 0) ? c0 : fmaf(powi16(A16, j), c0, P);

    float Ftail = fmaf(A16, cin, L);
    float F255  = __shfl_sync(FM, Ftail, 15, 16);
    float gin   = fmaf(powi16(A16, 15 - j), F255, Pb);

    float tf = cin, tb = gin;
    #pragma unroll
    for (int k = 0; k < CL; ++k) {
        const int ib = CL - 1 - k;
        tf = fmaf(a, tf, xv[k]);
        tb = fmaf(a, tb, xv[ib]);
        if (k < CL / 2) {
            Yv[k]  = tf;
            Yv[ib] = tb - xv[ib];
        } else {
            Yv[k]  += tf;
            Yv[ib] += tb - xv[ib];
        }
    }
}

// ---------------------------------------------------------------------------
// K1: horizontal pass for ONE batch n. CTA = (cblk, h). 512 thr (j,c).
// ---------------------------------------------------------------------------
__global__ void __launch_bounds__(NTHR, 2) hscan_k(const float* __restrict__ x,
                                                   int n) {
    const int cblk = blockIdx.x, h = blockIdx.y;
    extern __shared__ float sm1[];
    float* xs  = sm1;                     // [NJ][ISX][CT]
    float* ys0 = sm1 + NJ * JSX;
    float* ys1 = ys0 + NJ * JSY;

    const int tid = threadIdx.x;
    const float* src = x + ((size_t)(n * HH + h) * WW) * CC + cblk * CT;

    #pragma unroll
    for (int r = 0; r < 4; ++r) {
        int u = tid + r * NTHR;
        int w = u >> 3, cl = u & 7;
        float4 v = *(const float4*)(src + (size_t)w * CC + cl * 4);
        float* d = xs + (w >> 4) * JSX + (w & 15) * ISX + cl * 4;
        *(float2*)(d)     = make_float2(v.x, v.y);
        *(float2*)(d + 2) = make_float2(v.z, v.w);
    }
    __syncthreads();

    const int j = tid & 15;
    const int c = tid >> 4;

    float xv[CL];
    {
        const float* xp = xs + j * JSX + c;
        #pragma unroll
        for (int i = 0; i < CL; ++i) xv[i] = xp[i * ISX];
    }

    const int w2 = tid >> 1;
    const int hr = tid & 1;

    #pragma unroll
    for (int f = 0; f < NF; ++f) {
        const float a = c_a[f];
        const float A8 = powi16(a, 8);
        const float A16 = A8 * A8;
        const float cf = c_cf[f];

        float Yv[CL];
        scan_core(xv, Yv, j, a, A16, c_i1m[f]);

        float* ysb = (f & 1) ? ys1 : ys0;
        float* yp = ysb + j * JSY + c;
        #pragma unroll
        for (int i = 0; i < CL; ++i)
            yp[i * ISY] = cf * Yv[i];
        __syncthreads();

        {
            const float* yq = ysb + (w2 >> 4) * JSY + (w2 & 15) * ISY + hr * 16;
            float v0 = yq[0],  v1 = yq[1],  v2 = yq[2],  v3 = yq[3];
            float v4 = yq[4],  v5 = yq[5],  v6 = yq[6],  v7 = yq[7];
            float v8 = yq[8],  v9 = yq[9],  vA = yq[10], vB = yq[11];
            float vC = yq[12], vD = yq[13], vE = yq[14], vF = yq[15];
            uint4 o0, o1;
            o0.x = h2_bits(__floats2half2_rn(v0, v1));
            o0.y = h2_bits(__floats2half2_rn(v2, v3));
            o0.z = h2_bits(__floats2half2_rn(v4, v5));
            o0.w = h2_bits(__floats2half2_rn(v6, v7));
            o1.x = h2_bits(__floats2half2_rn(v8, v9));
            o1.y = h2_bits(__floats2half2_rn(vA, vB));
            o1.z = h2_bits(__floats2half2_rn(vC, vD));
            o1.w = h2_bits(__floats2half2_rn(vE, vF));
            __half* pb = g_mid + mid_base(f, cblk, w2) + (size_t)h * CT + hr * 16;
            *(uint4*)(pb)     = o0;
            *(uint4*)(pb + 8) = o1;
        }
    }
}

// ---------------------------------------------------------------------------
// K2: vertical pass for ONE batch n, channels-in-lanes. CTA = (cblk, w).
// ---------------------------------------------------------------------------
__global__ void __launch_bounds__(NTHR, 2) vscan_k(float* __restrict__ out,
                                                   const float* __restrict__ gl,
                                                   int n) {
    const int cblk = blockIdx.x, w = blockIdx.y;

    __shared__ float Ls [NF][NJ][CT];   // forward chunk tails
    __shared__ float LBs[NF][NJ][CT];   // backward chunk heads
    __shared__ float X0s[NF][CT];       // first element of column (h=0)
    __shared__ float wsm[NF][CT];       // softmax * cf

    const int tid = threadIdx.x;
    const int c = tid & 31;
    const int j = tid >> 5;             // warp-uniform

    if (tid < CT) {
        int cg = cblk * CT + tid;
        float v0 = gl[0 * CC + cg], v1 = gl[1 * CC + cg];
        float v2 = gl[2 * CC + cg], v3 = gl[3 * CC + cg];
        float m = fmaxf(fmaxf(v0, v1), fmaxf(v2, v3));
        float e0 = expf(v0 - m), e1 = expf(v1 - m);
        float e2 = expf(v2 - m), e3 = expf(v3 - m);
        float r = 1.0f / (e0 + e1 + e2 + e3);
        wsm[0][tid] = e0 * r * c_cf[0];
        wsm[1][tid] = e1 * r * c_cf[1];
        wsm[2][tid] = e2 * r * c_cf[2];
        wsm[3][tid] = e3 * r * c_cf[3];
    }

    float Ysum[CL];
    #pragma unroll
    for (int i = 0; i < CL; ++i) Ysum[i] = 0.0f;

    #pragma unroll
    for (int f = 0; f < NF; ++f) {
        const float a = c_a[f];
        const float A8 = powi16(a, 8);
        const float A16 = A8 * A8;

        // load 16 values: warp-contiguous 64B rows, fully coalesced (L2-hot)
        float xv[CL];
        {
            const __half* mp = g_mid + mid_base(f, cblk, w)
                             + (size_t)(j * CL) * CT + c;
            #pragma unroll
            for (int i = 0; i < CL; ++i)
                xv[i] = __half2float(mp[(size_t)i * CT]);
        }

        // local zero-carry scans
        float L = 0.0f, LB = 0.0f;
        #pragma unroll
        for (int i = 0; i < CL; ++i) {
            L  = fmaf(a, L,  xv[i]);
            LB = fmaf(a, LB, xv[CL - 1 - i]);
        }
        Ls [f][j][c] = L;
        LBs[f][j][c] = LB;
        if (j == 0) X0s[f][c] = xv[0];
        __syncthreads();

        // carry chains (Horner over smem; capture at warp-uniform m==j)
        float c0 = X0s[f][c] * c_i1m[f];
        float p = c0, cin = c0;
        #pragma unroll
        for (int m = 0; m < NJ; ++m) {
            if (m == j) cin = p;
            p = fmaf(A16, p, Ls[f][m][c]);
        }
        float F255 = p;
        float q = F255, gin = F255;
        #pragma unroll
        for (int m = NJ - 1; m >= 0; --m) {
            if (m == j) gin = q;
            q = fmaf(A16, q, LBs[f][m][c]);
        }

        // fused recompute + weighted accumulate
        const float wt = wsm[f][c];
        float tf = cin, tb = gin;
        #pragma unroll
        for (int k = 0; k < CL; ++k) {
            const int ib = CL - 1 - k;
            tf = fmaf(a, tf, xv[k]);
            tb = fmaf(a, tb, xv[ib]);
            Ysum[k]  = fmaf(wt, tf, Ysum[k]);
            Ysum[ib] = fmaf(wt, tb - xv[ib], Ysum[ib]);
        }
    }

    // output: full 128B-line stores straight from registers
    {
        float* ob = out + ((size_t)(n * HH + j * CL) * WW + w) * CC + cblk * CT + c;
        #pragma unroll
        for (int i = 0; i < CL; ++i)
            ob[(size_t)i * WW * CC] = Ysum[i];
    }
}

// ---------------------------------------------------------------------------
extern "C" void kernel_launch(void* const* d_in, const int* in_sizes, int n_in,
                              void* d_out, int out_size) {
    const float* x  = (const float*)d_in[0];
    const float* gl = (const float*)d_in[1];
    float* out = (float*)d_out;

    const int smem1 = (NJ * JSX + 2 * NJ * JSY) * (int)sizeof(float);
    cudaFuncSetAttribute(hscan_k, cudaFuncAttributeMaxDynamicSharedMemorySize, smem1);

    dim3 g1(NCB, HH, 1);
    dim3 g2(NCB, WW, 1);

    // interleave per-batch pairs: the 50MB intermediate stays L2-resident
    // between hscan_n and vscan_n, and is overwritten by hscan_{n+1} before
    // most dirty lines would be evicted to DRAM.
    for (int n = 0; n < NB; ++n) {
        hscan_k<<<g1, NTHR, smem1>>>(x, n);
        vscan_k<<<g2, NTHR>>>(out, gl, n);
    }

    (void)in_sizes; (void)n_in; (void)out_size;
}

// round 14
// speedup vs baseline: 1.3419x; 1.3419x over previous
#include <cuda_runtime.h>
#include <cuda_fp16.h>
#include <cstdint>
#include <cstddef>

#define NB 4
#define HH 256
#define WW 256
#define CC 96
#define NF 4
#define CT 32                   // channels per CTA
#define NCB (CC / CT)           // 3 channel blocks
#define NJ 16                   // chunks per row/column
#define CL 16                   // chunk length
#define NTHR 512                // NJ * CT

__constant__ float c_a[NF]   = {0.1f, 0.3f, 0.4f, 0.8f};
__constant__ float c_cf[NF]  = {0.81818181818f, 0.53846153846f, 0.42857142857f, 0.11111111111f}; // (1-a)/(1+a)
__constant__ float c_i1m[NF] = {1.11111111111f, 1.42857142857f, 1.66666666667f, 5.0f};           // 1/(1-a)

// intermediate: [f][n][cblk][w][h][c32]
#define COLSZ ((size_t)HH * CT)                 // 8192 halves per (w) column
__device__ __half g_mid[(size_t)NF * NB * NCB * WW * COLSZ];
__device__ __forceinline__ size_t mid_base(int f, int n, int cblk) {
    return (((size_t)f * NB + n) * NCB + cblk) * ((size_t)WW * COLSZ);
}

__device__ __forceinline__ float powi16(float A, int e) {
    float r = 1.0f, p = A;
    if (e & 1) r *= p;  p *= p;
    if (e & 2) r *= p;  p *= p;
    if (e & 4) r *= p;  p *= p;
    if (e & 8) r *= p;
    return r;
}

// ---------------------------------------------------------------------------
// K1: horizontal pass, channels-in-lanes. CTA = (cblk, h, n).
// 512 threads: c = tid&31 (lane), j = tid>>5 (warp-uniform chunk of w).
// Register-resident; smem only for chunk-carry exchange. ONE barrier.
// ---------------------------------------------------------------------------
__global__ void __launch_bounds__(NTHR, 2) hscan_k(const float* __restrict__ x) {
    const int cblk = blockIdx.x, h = blockIdx.y, n = blockIdx.z;

    __shared__ float Ls [NF][NJ][CT];   // forward chunk tails (per filter)
    __shared__ float LBs[NF][NJ][CT];   // backward chunk heads
    __shared__ float X0s[CT];           // x at w=0 (filter-independent)

    const int tid = threadIdx.x;
    const int c = tid & 31;
    const int j = tid >> 5;             // warp-uniform chunk index

    // ---- load 16 x values along w: warp-contiguous 128B per step ----
    float xv[CL];
    {
        const float* xp = x + (((size_t)(n * HH + h)) * WW + j * CL) * CC
                        + cblk * CT + c;
        #pragma unroll
        for (int i = 0; i < CL; ++i) xv[i] = xp[(size_t)i * CC];
    }

    // ---- local zero-carry scans for ALL 4 filters in one pass (8 chains) ----
    {
        float Lf0 = 0.f, Lf1 = 0.f, Lf2 = 0.f, Lf3 = 0.f;
        float Bf0 = 0.f, Bf1 = 0.f, Bf2 = 0.f, Bf3 = 0.f;
        #pragma unroll
        for (int i = 0; i < CL; ++i) {
            float xf = xv[i], xb = xv[CL - 1 - i];
            Lf0 = fmaf(c_a[0], Lf0, xf);  Bf0 = fmaf(c_a[0], Bf0, xb);
            Lf1 = fmaf(c_a[1], Lf1, xf);  Bf1 = fmaf(c_a[1], Bf1, xb);
            Lf2 = fmaf(c_a[2], Lf2, xf);  Bf2 = fmaf(c_a[2], Bf2, xb);
            Lf3 = fmaf(c_a[3], Lf3, xf);  Bf3 = fmaf(c_a[3], Bf3, xb);
        }
        Ls[0][j][c] = Lf0;  LBs[0][j][c] = Bf0;
        Ls[1][j][c] = Lf1;  LBs[1][j][c] = Bf1;
        Ls[2][j][c] = Lf2;  LBs[2][j][c] = Bf2;
        Ls[3][j][c] = Lf3;  LBs[3][j][c] = Bf3;
        if (j == 0) X0s[c] = xv[0];
    }
    __syncthreads();                    // the only barrier

    // ---- per filter: Horner carries, fused recompute, direct fp16 store ----
    #pragma unroll
    for (int f = 0; f < NF; ++f) {
        const float a = c_a[f];
        const float A8 = powi16(a, 8);
        const float A16 = A8 * A8;
        const float cf = c_cf[f];

        float c0 = X0s[c] * c_i1m[f];
        float p = c0, cin = c0;
        #pragma unroll
        for (int m = 0; m < NJ; ++m) {
            if (m == j) cin = p;                 // uniform branch
            p = fmaf(A16, p, Ls[f][m][c]);
        }
        float Wlast = p;                         // F at w=255 (full forward tail)
        float q = Wlast, gin = Wlast;
        #pragma unroll
        for (int m = NJ - 1; m >= 0; --m) {
            if (m == j) gin = q;                 // uniform branch
            q = fmaf(A16, q, LBs[f][m][c]);
        }

        float Yv[CL];
        float tf = cin, tb = gin;
        #pragma unroll
        for (int k = 0; k < CL; ++k) {
            const int ib = CL - 1 - k;
            tf = fmaf(a, tf, xv[k]);
            tb = fmaf(a, tb, xv[ib]);
            if (k < CL / 2) {
                Yv[k]  = tf;
                Yv[ib] = tb - xv[ib];
            } else {
                Yv[k]  += tf;
                Yv[ib] += tb - xv[ib];
            }
        }

        // store: warp writes 64B contiguous per step ([w][h][c32] layout)
        __half* mp = g_mid + mid_base(f, n, cblk)
                   + (size_t)(j * CL) * COLSZ + (size_t)h * CT + c;
        #pragma unroll
        for (int k = 0; k < CL; ++k)
            mp[(size_t)k * COLSZ] = __float2half(cf * Yv[k]);
    }
}

// ---------------------------------------------------------------------------
// K2: vertical pass, channels-in-lanes (R12 structure). CTA = (cblk, w, n).
// ---------------------------------------------------------------------------
__global__ void __launch_bounds__(NTHR, 2) vscan_k(float* __restrict__ out,
                                                   const float* __restrict__ gl) {
    const int cblk = blockIdx.x, w = blockIdx.y, n = blockIdx.z;

    __shared__ float Ls [NF][NJ][CT];
    __shared__ float LBs[NF][NJ][CT];
    __shared__ float X0s[NF][CT];
    __shared__ float wsm[NF][CT];

    const int tid = threadIdx.x;
    const int c = tid & 31;
    const int j = tid >> 5;

    if (tid < CT) {
        int cg = cblk * CT + tid;
        float v0 = gl[0 * CC + cg], v1 = gl[1 * CC + cg];
        float v2 = gl[2 * CC + cg], v3 = gl[3 * CC + cg];
        float m = fmaxf(fmaxf(v0, v1), fmaxf(v2, v3));
        float e0 = expf(v0 - m), e1 = expf(v1 - m);
        float e2 = expf(v2 - m), e3 = expf(v3 - m);
        float r = 1.0f / (e0 + e1 + e2 + e3);
        wsm[0][tid] = e0 * r * c_cf[0];
        wsm[1][tid] = e1 * r * c_cf[1];
        wsm[2][tid] = e2 * r * c_cf[2];
        wsm[3][tid] = e3 * r * c_cf[3];
    }

    float Ysum[CL];
    #pragma unroll
    for (int i = 0; i < CL; ++i) Ysum[i] = 0.0f;

    #pragma unroll
    for (int f = 0; f < NF; ++f) {
        const float a = c_a[f];
        const float A8 = powi16(a, 8);
        const float A16 = A8 * A8;

        float xv[CL];
        {
            const __half* mp = g_mid + mid_base(f, n, cblk)
                             + ((size_t)w * HH + j * CL) * CT + c;
            #pragma unroll
            for (int i = 0; i < CL; ++i)
                xv[i] = __half2float(mp[(size_t)i * CT]);
        }

        float L = 0.0f, LB = 0.0f;
        #pragma unroll
        for (int i = 0; i < CL; ++i) {
            L  = fmaf(a, L,  xv[i]);
            LB = fmaf(a, LB, xv[CL - 1 - i]);
        }
        Ls [f][j][c] = L;
        LBs[f][j][c] = LB;
        if (j == 0) X0s[f][c] = xv[0];
        __syncthreads();

        float c0 = X0s[f][c] * c_i1m[f];
        float p = c0, cin = c0;
        #pragma unroll
        for (int m = 0; m < NJ; ++m) {
            if (m == j) cin = p;
            p = fmaf(A16, p, Ls[f][m][c]);
        }
        float F255 = p;
        float q = F255, gin = F255;
        #pragma unroll
        for (int m = NJ - 1; m >= 0; --m) {
            if (m == j) gin = q;
            q = fmaf(A16, q, LBs[f][m][c]);
        }

        const float wt = wsm[f][c];
        float tf = cin, tb = gin;
        #pragma unroll
        for (int k = 0; k < CL; ++k) {
            const int ib = CL - 1 - k;
            tf = fmaf(a, tf, xv[k]);
            tb = fmaf(a, tb, xv[ib]);
            Ysum[k]  = fmaf(wt, tf, Ysum[k]);
            Ysum[ib] = fmaf(wt, tb - xv[ib], Ysum[ib]);
        }
    }

    {
        float* ob = out + ((size_t)(n * HH + j * CL) * WW + w) * CC + cblk * CT + c;
        #pragma unroll
        for (int i = 0; i < CL; ++i)
            ob[(size_t)i * WW * CC] = Ysum[i];
    }
}

// ---------------------------------------------------------------------------
extern "C" void kernel_launch(void* const* d_in, const int* in_sizes, int n_in,
                              void* d_out, int out_size) {
    const float* x  = (const float*)d_in[0];
    const float* gl = (const float*)d_in[1];
    float* out = (float*)d_out;

    dim3 g1(NCB, HH, NB);
    hscan_k<<<g1, NTHR>>>(x);

    dim3 g2(NCB, WW, NB);
    vscan_k<<<g2, NTHR>>>(out, gl);

    (void)in_sizes; (void)n_in; (void)out_size;
}

// round 15
// speedup vs baseline: 1.6782x; 1.2506x over previous
#include <cuda_runtime.h>
#include <cuda_fp16.h>
#include <cstdint>
#include <cstddef>

#define NB 4
#define HH 256
#define WW 256
#define CC 96
#define NF 4
#define CT 32                   // channels per CTA
#define NCB (CC / CT)           // 3 channel blocks
#define NJ 16                   // chunks per row/column
#define CL 16                   // chunk length
#define NTHR 512                // NJ * CT

// compile-time filter coefficient powers (guaranteed immediates)
template<int F> struct FA { static constexpr float v = (F==0)?0.1f:(F==1)?0.3f:(F==2)?0.4f:0.8f; };
template<int F, int E> struct PW { static constexpr float v = PW<F,E-1>::v * FA<F>::v; };
template<int F> struct PW<F,0> { static constexpr float v = 1.0f; };

__constant__ float c_a[NF]   = {0.1f, 0.3f, 0.4f, 0.8f};
__constant__ float c_cf[NF]  = {0.81818181818f, 0.53846153846f, 0.42857142857f, 0.11111111111f}; // (1-a)/(1+a)
__constant__ float c_i1m[NF] = {1.11111111111f, 1.42857142857f, 1.66666666667f, 5.0f};           // 1/(1-a)
__constant__ float c_A16[NF] = {1.0e-16f, 4.3046721e-9f, 4.2949673e-7f, 2.8147498e-2f};          // a^16

// intermediate: [f][n][cblk][w][h][c32]
#define COLSZ ((size_t)HH * CT)                 // 8192 halves per (w) column
__device__ __half g_mid[(size_t)NF * NB * NCB * WW * COLSZ];
__device__ __forceinline__ size_t mid_base(int f, int n, int cblk) {
    return (((size_t)f * NB + n) * NCB + cblk) * ((size_t)WW * COLSZ);
}

// parallel carry-correction epilogue: Y[i] += a^{i+1}*u + a^{16-i}*v  (immediates)
template<int F>
__device__ __forceinline__ void epi_add(float u, float v, float* __restrict__ Y) {
#define EPI(i) Y[i] = fmaf(PW<F,(i)+1>::v, u, fmaf(PW<F,CL-(i)>::v, v, Y[i]));
    EPI(0)  EPI(1)  EPI(2)  EPI(3)  EPI(4)  EPI(5)  EPI(6)  EPI(7)
    EPI(8)  EPI(9)  EPI(10) EPI(11) EPI(12) EPI(13) EPI(14) EPI(15)
#undef EPI
}

// ---------------------------------------------------------------------------
// K1: horizontal pass. CTA = (cblk, h, n). c = lane, j = warp (chunk of w).
// phase A (zero-carry tails, all filters) -> bar -> dedup Horner (warps 0-3)
// -> bar -> per-filter recompute-with-carry + fp16 store.
// ---------------------------------------------------------------------------
__global__ void __launch_bounds__(NTHR, 2) hscan_k(const float* __restrict__ x) {
    const int cblk = blockIdx.x, h = blockIdx.y, n = blockIdx.z;

    __shared__ float Ls  [NF][NJ][CT];
    __shared__ float LBs [NF][NJ][CT];
    __shared__ float cinS[NF][NJ][CT];
    __shared__ float ginS[NF][NJ][CT];
    __shared__ float X0s[CT];

    const int tid = threadIdx.x;
    const int c = tid & 31;
    const int j = tid >> 5;

    // load 16 x values along w: warp-contiguous 128B per step
    float xv[CL];
    {
        const float* xp = x + (((size_t)(n * HH + h)) * WW + j * CL) * CC
                        + cblk * CT + c;
        #pragma unroll
        for (int i = 0; i < CL; ++i) xv[i] = xp[(size_t)i * CC];
    }

    // zero-carry tails for all 4 filters in one pass (8 chains, high ILP)
    {
        float Lf0 = 0.f, Lf1 = 0.f, Lf2 = 0.f, Lf3 = 0.f;
        float Bf0 = 0.f, Bf1 = 0.f, Bf2 = 0.f, Bf3 = 0.f;
        #pragma unroll
        for (int i = 0; i < CL; ++i) {
            float xf = xv[i], xb = xv[CL - 1 - i];
            Lf0 = fmaf(c_a[0], Lf0, xf);  Bf0 = fmaf(c_a[0], Bf0, xb);
            Lf1 = fmaf(c_a[1], Lf1, xf);  Bf1 = fmaf(c_a[1], Bf1, xb);
            Lf2 = fmaf(c_a[2], Lf2, xf);  Bf2 = fmaf(c_a[2], Bf2, xb);
            Lf3 = fmaf(c_a[3], Lf3, xf);  Bf3 = fmaf(c_a[3], Bf3, xb);
        }
        Ls[0][j][c] = Lf0;  LBs[0][j][c] = Bf0;
        Ls[1][j][c] = Lf1;  LBs[1][j][c] = Bf1;
        Ls[2][j][c] = Lf2;  LBs[2][j][c] = Bf2;
        Ls[3][j][c] = Lf3;  LBs[3][j][c] = Bf3;
        if (j == 0) X0s[c] = xv[0];
    }
    __syncthreads();

    // dedup Horner: warp f computes filter-f carry chain once per channel,
    // storing every capture point.
    if (j < NF) {
        const int f = j;
        const float A16 = c_A16[f];
        float p = X0s[c] * c_i1m[f];
        #pragma unroll
        for (int m = 0; m < NJ; ++m) {
            cinS[f][m][c] = p;
            p = fmaf(A16, p, Ls[f][m][c]);
        }
        float q = p;                              // full forward tail (w=255)
        #pragma unroll
        for (int m = NJ - 1; m >= 0; --m) {
            ginS[f][m][c] = q;
            q = fmaf(A16, q, LBs[f][m][c]);
        }
    }
    __syncthreads();

    // per-filter recompute with true carries + direct fp16 store
    #pragma unroll
    for (int f = 0; f < NF; ++f) {
        const float a  = c_a[f];
        const float cf = c_cf[f];
        float tf = cinS[f][j][c];
        float tb = ginS[f][j][c];
        float Yv[CL];
        #pragma unroll
        for (int k = 0; k < CL; ++k) {
            const int ib = CL - 1 - k;
            tf = fmaf(a, tf, xv[k]);
            tb = fmaf(a, tb, xv[ib]);
            if (k < CL / 2) {
                Yv[k]  = tf;
                Yv[ib] = tb - xv[ib];
            } else {
                Yv[k]  += tf;
                Yv[ib] += tb - xv[ib];
            }
        }
        __half* mp = g_mid + mid_base(f, n, cblk)
                   + (size_t)(j * CL) * COLSZ + (size_t)h * CT + c;
        #pragma unroll
        for (int k = 0; k < CL; ++k)
            mp[(size_t)k * COLSZ] = __float2half(cf * Yv[k]);
    }
}

// ---------------------------------------------------------------------------
// K2: vertical pass. CTA = (cblk, w, n). c = lane, j = warp (chunk of h).
// phase 1: fused zero-carry pass accumulating wt*S into Ysum + tails ->
// bar -> dedup Horner -> bar -> parallel immediate-power carry correction.
// ---------------------------------------------------------------------------
__global__ void __launch_bounds__(NTHR, 2) vscan_k(float* __restrict__ out,
                                                   const float* __restrict__ gl) {
    const int cblk = blockIdx.x, w = blockIdx.y, n = blockIdx.z;

    __shared__ float Ls  [NF][NJ][CT];
    __shared__ float LBs [NF][NJ][CT];
    __shared__ float cinS[NF][NJ][CT];
    __shared__ float ginS[NF][NJ][CT];
    __shared__ float X0s[NF][CT];

    const int tid = threadIdx.x;
    const int c = tid & 31;
    const int j = tid >> 5;

    // per-thread softmax weights (wt_f = softmax_f(c) * cf_f)
    float wt[NF];
    {
        const int cg = cblk * CT + c;
        float v0 = gl[0 * CC + cg], v1 = gl[1 * CC + cg];
        float v2 = gl[2 * CC + cg], v3 = gl[3 * CC + cg];
        float m = fmaxf(fmaxf(v0, v1), fmaxf(v2, v3));
        float e0 = __expf(v0 - m), e1 = __expf(v1 - m);
        float e2 = __expf(v2 - m), e3 = __expf(v3 - m);
        float r = __fdividef(1.0f, e0 + e1 + e2 + e3);
        wt[0] = e0 * r * c_cf[0];
        wt[1] = e1 * r * c_cf[1];
        wt[2] = e2 * r * c_cf[2];
        wt[3] = e3 * r * c_cf[3];
    }

    float Ysum[CL];
    #pragma unroll
    for (int i = 0; i < CL; ++i) Ysum[i] = 0.0f;

    // phase 1: per filter, fused zero-carry pass (accumulates wt*S, yields tails)
    #pragma unroll
    for (int f = 0; f < NF; ++f) {
        const float a  = c_a[f];
        const float wf = wt[f];

        float xv[CL];
        {
            const __half* mp = g_mid + mid_base(f, n, cblk)
                             + ((size_t)w * HH + j * CL) * CT + c;
            #pragma unroll
            for (int i = 0; i < CL; ++i)
                xv[i] = __half2float(mp[(size_t)i * CT]);
        }

        float tf = 0.0f, tb = 0.0f;
        #pragma unroll
        for (int k = 0; k < CL; ++k) {
            const int ib = CL - 1 - k;
            tf = fmaf(a, tf, xv[k]);              // localF[k]
            tb = fmaf(a, tb, xv[ib]);             // localB[ib]
            Ysum[k]  = fmaf(wf, tf, Ysum[k]);
            Ysum[ib] = fmaf(wf, tb - xv[ib], Ysum[ib]);
        }
        Ls [f][j][c] = tf;
        LBs[f][j][c] = tb;
        if (j == 0) X0s[f][c] = xv[0];
    }
    __syncthreads();

    // dedup Horner (warps 0-3, one filter each)
    if (j < NF) {
        const int f = j;
        const float A16 = c_A16[f];
        float p = X0s[f][c] * c_i1m[f];
        #pragma unroll
        for (int m = 0; m < NJ; ++m) {
            cinS[f][m][c] = p;
            p = fmaf(A16, p, Ls[f][m][c]);
        }
        float q = p;
        #pragma unroll
        for (int m = NJ - 1; m >= 0; --m) {
            ginS[f][m][c] = q;
            q = fmaf(A16, q, LBs[f][m][c]);
        }
    }
    __syncthreads();

    // parallel carry correction (immediate powers, 2 FFMA per element/filter)
    epi_add<0>(wt[0] * cinS[0][j][c], wt[0] * ginS[0][j][c], Ysum);
    epi_add<1>(wt[1] * cinS[1][j][c], wt[1] * ginS[1][j][c], Ysum);
    epi_add<2>(wt[2] * cinS[2][j][c], wt[2] * ginS[2][j][c], Ysum);
    epi_add<3>(wt[3] * cinS[3][j][c], wt[3] * ginS[3][j][c], Ysum);

    // output: full 128B-line stores straight from registers
    {
        float* ob = out + ((size_t)(n * HH + j * CL) * WW + w) * CC + cblk * CT + c;
        #pragma unroll
        for (int i = 0; i < CL; ++i)
            ob[(size_t)i * WW * CC] = Ysum[i];
    }
}

// ---------------------------------------------------------------------------
extern "C" void kernel_launch(void* const* d_in, const int* in_sizes, int n_in,
                              void* d_out, int out_size) {
    const float* x  = (const float*)d_in[0];
    const float* gl = (const float*)d_in[1];
    float* out = (float*)d_out;

    dim3 g1(NCB, HH, NB);
    hscan_k<<<g1, NTHR>>>(x);

    dim3 g2(NCB, WW, NB);
    vscan_k<<<g2, NTHR>>>(out, gl);

    (void)in_sizes; (void)n_in; (void)out_size;
}